// round 13
// baseline (speedup 1.0000x reference)
#include <cuda_runtime.h>
#include <cuda_bf16.h>

#define SQ    256
#define BATCH 16
#define EMB   512
#define HID   256
#define HMD   128
#define G4    1024            // 4*HID
#define NROWS (SQ*BATCH)      // 4096
#define INW   512             // input width both layers (E = 2H = 512)
#define NSC   (BATCH*SQ*SQ)   // 1,048,576 scores

// ---------------- scratch (device globals; no allocations allowed) ----------
__device__ float g_xa[NROWS * EMB];                 // 8 MB
__device__ float g_xb[NROWS * EMB];                 // 8 MB
__device__ float g_xproj[2 * SQ * G4 * BATCH];      // 32 MB : [dir][t][gate(1024)][b]
__device__ float g_p[BATCH * SQ * HMD];             // 2 MB
__device__ float g_cq[BATCH * SQ * HMD];            // 2 MB
// bf16 split operands (hi/lo), written by split_kernel per layer
__device__ uint2 g_a1[NROWS * EMB / 4];             // 4 MB (bf16 4096x512)
__device__ uint2 g_a2[NROWS * EMB / 4];             // 4 MB
__device__ uint2 g_w1[2 * G4 * EMB / 4];            // 2 MB (bf16 2048x512)
__device__ uint2 g_w2[2 * G4 * EMB / 4];            // 2 MB

// ---------------- f32x2 packed math ------------------------------------------
__device__ __forceinline__ unsigned long long ffma2(unsigned long long a,
                                                    unsigned long long b,
                                                    unsigned long long c) {
    unsigned long long d;
    asm("fma.rn.f32x2 %0, %1, %2, %3;" : "=l"(d) : "l"(a), "l"(b), "l"(c));
    return d;
}
__device__ __forceinline__ unsigned long long pack2(float x, float y) {
    unsigned long long d;
    asm("mov.b64 %0, {%1, %2};" : "=l"(d) : "f"(x), "f"(y));
    return d;
}
__device__ __forceinline__ float2 unpack2(unsigned long long v) {
    float2 r;
    asm("mov.b64 {%0, %1}, %2;" : "=f"(r.x), "=f"(r.y) : "l"(v));
    return r;
}

// ---------------- cluster / mbarrier helpers ---------------------------------
__device__ __forceinline__ unsigned smem_u32(const void* p) {
    unsigned a;
    asm("{ .reg .u64 t; cvta.to.shared.u64 t, %1; cvt.u32.u64 %0, t; }"
        : "=r"(a) : "l"(p));
    return a;
}
__device__ __forceinline__ unsigned mapa_u32(unsigned addr, unsigned rank) {
    unsigned r;
    asm("mapa.shared::cluster.u32 %0, %1, %2;" : "=r"(r) : "r"(addr), "r"(rank));
    return r;
}
__device__ __forceinline__ void st_cluster_v4(unsigned addr, float4 v) {
    asm volatile("st.shared::cluster.v4.f32 [%0], {%1, %2, %3, %4};"
                 :: "r"(addr), "f"(v.x), "f"(v.y), "f"(v.z), "f"(v.w) : "memory");
}
__device__ __forceinline__ void mbar_init(unsigned addr, unsigned cnt) {
    asm volatile("mbarrier.init.shared.b64 [%0], %1;" :: "r"(addr), "r"(cnt) : "memory");
}
__device__ __forceinline__ void mbar_arrive_rank(unsigned local_mbar, unsigned rank) {
    asm volatile(
        "{ .reg .b32 ra; mapa.shared::cluster.u32 ra, %0, %1;\n\t"
        "mbarrier.arrive.release.cluster.shared::cluster.b64 _, [ra]; }"
        :: "r"(local_mbar), "r"(rank) : "memory");
}
__device__ __forceinline__ void mbar_wait(unsigned mbar, unsigned parity) {
    unsigned done = 0;
    while (!done) {
        asm volatile(
            "{ .reg .pred p;\n\t"
            "mbarrier.try_wait.parity.acquire.cluster.shared::cta.b64 p, [%1], %2, 0x989680;\n\t"
            "selp.b32 %0, 1, 0, p; }"
            : "=r"(done) : "r"(mbar), "r"(parity) : "memory");
    }
}

// ---------------- bf16 split helper ------------------------------------------
__device__ __forceinline__ void split4(float4 v, uint2& hi, uint2& lo) {
    __nv_bfloat16 a0 = __float2bfloat16(v.x), a1 = __float2bfloat16(v.y);
    __nv_bfloat16 a2 = __float2bfloat16(v.z), a3 = __float2bfloat16(v.w);
    float r0 = v.x - __bfloat162float(a0), r1 = v.y - __bfloat162float(a1);
    float r2 = v.z - __bfloat162float(a2), r3 = v.w - __bfloat162float(a3);
    __nv_bfloat16 b0 = __float2bfloat16(r0), b1 = __float2bfloat16(r1);
    __nv_bfloat16 b2 = __float2bfloat16(r2), b3 = __float2bfloat16(r3);
    hi.x = ((unsigned)__bfloat16_as_ushort(a1) << 16) | __bfloat16_as_ushort(a0);
    hi.y = ((unsigned)__bfloat16_as_ushort(a3) << 16) | __bfloat16_as_ushort(a2);
    lo.x = ((unsigned)__bfloat16_as_ushort(b1) << 16) | __bfloat16_as_ushort(b0);
    lo.y = ((unsigned)__bfloat16_as_ushort(b3) << 16) | __bfloat16_as_ushort(b2);
}

// ---------------- scalar math helpers ----------------------------------------
__device__ __forceinline__ float ftanh(float x) {
    x = fminf(fmaxf(x, -15.f), 15.f);
    float e = __expf(2.f * x);
    return 1.f - __fdividef(2.f, e + 1.f);
}
__device__ __forceinline__ float fsig(float x) {
    x = fminf(fmaxf(x, -30.f), 30.f);
    return __fdividef(1.f, 1.f + __expf(-x));
}

// ---------------- 0) noop (x1: shifts ncu -s 5 onto lstm_rec L0) -------------
__global__ void noop_kernel() {}

// ---------------- 1) embedding gather ----------------------------------------
__global__ __launch_bounds__(128) void embed_kernel(const int* __restrict__ concepts,
                                                    const float* __restrict__ emb) {
    int row = blockIdx.x;                       // s*16 + b
    int tok = concepts[row];
    const float4* src = (const float4*)(emb + (size_t)tok * EMB);
    float4* dst = (float4*)(g_xa + (size_t)row * EMB);
    dst[threadIdx.x] = src[threadIdx.x];        // 128 * float4 = 512 floats
}

// ---------------- 1b) fp32 -> bf16 hi/lo split -------------------------------
__global__ __launch_bounds__(256) void split_kernel(const float4* __restrict__ src,
                                                    uint2* __restrict__ d1,
                                                    uint2* __restrict__ d2, int n4) {
    int stride = gridDim.x * blockDim.x;
    for (int i = blockIdx.x * blockDim.x + threadIdx.x; i < n4; i += stride) {
        float4 v = src[i];
        uint2 h, l;
        split4(v, h, l);
        d1[i] = h;
        d2[i] = l;
    }
}

// ---------------- 2) input projection via mma.sync bf16x3 --------------------
// C[4096,2048] = A[4096,512] x W[2048,512]^T ~= A1W1 + A1W2 + A2W1 (fp32 acc).
// CTA tile 128x128, warp 64x32, m16n8k16, K-chunk 32, smem rows padded to 40.
#define MMA_BF16(c, a, b)                                                       \
    asm volatile(                                                               \
        "mma.sync.aligned.m16n8k16.row.col.f32.bf16.bf16.f32 "                  \
        "{%0,%1,%2,%3}, {%4,%5,%6,%7}, {%8,%9}, {%0,%1,%2,%3};"                 \
        : "+f"((c)[0]), "+f"((c)[1]), "+f"((c)[2]), "+f"((c)[3])                \
        : "r"((a)[0]), "r"((a)[1]), "r"((a)[2]), "r"((a)[3]),                   \
          "r"((b)[0]), "r"((b)[1]))

__global__ __launch_bounds__(256, 2) void inproj_mma_kernel(const float* __restrict__ bias) {
    __shared__ __align__(16) unsigned short As1[128][40];
    __shared__ __align__(16) unsigned short As2[128][40];
    __shared__ __align__(16) unsigned short Ws1[128][40];
    __shared__ __align__(16) unsigned short Ws2[128][40];
    int tid = threadIdx.x, wid = tid >> 5, lane = tid & 31;
    int n0 = blockIdx.x << 7, m0 = blockIdx.y << 7;
    int wm = wid >> 2, wn = wid & 3;           // warp tile: (wm*64, wn*32)
    int g = lane >> 2, t4 = lane & 3;

    const uint4* A1 = (const uint4*)g_a1;      // [4096][64] uint4 (8 bf16 each)
    const uint4* A2 = (const uint4*)g_a2;
    const uint4* W1 = (const uint4*)g_w1;      // [2048][64] uint4
    const uint4* W2 = (const uint4*)g_w2;

    float acc[4][4][4];
#pragma unroll
    for (int mt = 0; mt < 4; mt++)
#pragma unroll
        for (int nt = 0; nt < 4; nt++)
#pragma unroll
            for (int i = 0; i < 4; i++) acc[mt][nt][i] = 0.f;

    for (int ch = 0; ch < 16; ch++) {
        int kb = (ch << 2);                    // uint4 offset within row (ch*32/8)
        uint4 ra1[2], ra2[2], rw1[2], rw2[2];
        int r0 = (tid * 2) >> 2, c0 = (tid * 2) & 3;
        int r1 = (tid * 2 + 1) >> 2, c1 = (tid * 2 + 1) & 3;
        ra1[0] = A1[(size_t)(m0 + r0) * 64 + kb + c0];
        ra1[1] = A1[(size_t)(m0 + r1) * 64 + kb + c1];
        ra2[0] = A2[(size_t)(m0 + r0) * 64 + kb + c0];
        ra2[1] = A2[(size_t)(m0 + r1) * 64 + kb + c1];
        rw1[0] = W1[(size_t)(n0 + r0) * 64 + kb + c0];
        rw1[1] = W1[(size_t)(n0 + r1) * 64 + kb + c1];
        rw2[0] = W2[(size_t)(n0 + r0) * 64 + kb + c0];
        rw2[1] = W2[(size_t)(n0 + r1) * 64 + kb + c1];
        __syncthreads();                       // prev compute done
        *(uint4*)&As1[r0][c0 << 3] = ra1[0];
        *(uint4*)&As1[r1][c1 << 3] = ra1[1];
        *(uint4*)&As2[r0][c0 << 3] = ra2[0];
        *(uint4*)&As2[r1][c1 << 3] = ra2[1];
        *(uint4*)&Ws1[r0][c0 << 3] = rw1[0];
        *(uint4*)&Ws1[r1][c1 << 3] = rw1[1];
        *(uint4*)&Ws2[r0][c0 << 3] = rw2[0];
        *(uint4*)&Ws2[r1][c1 << 3] = rw2[1];
        __syncthreads();

#pragma unroll
        for (int k16 = 0; k16 < 2; k16++) {
            int kk = k16 << 4;
            unsigned b1f[4][2], b2f[4][2];
#pragma unroll
            for (int nt = 0; nt < 4; nt++) {
                int nr = (wn << 5) + (nt << 3) + g;
                b1f[nt][0] = *(const unsigned*)&Ws1[nr][kk + (t4 << 1)];
                b1f[nt][1] = *(const unsigned*)&Ws1[nr][kk + 8 + (t4 << 1)];
                b2f[nt][0] = *(const unsigned*)&Ws2[nr][kk + (t4 << 1)];
                b2f[nt][1] = *(const unsigned*)&Ws2[nr][kk + 8 + (t4 << 1)];
            }
#pragma unroll
            for (int mt = 0; mt < 4; mt++) {
                int mr = (wm << 6) + (mt << 4);
                unsigned a1f[4], a2f[4];
                a1f[0] = *(const unsigned*)&As1[mr + g][kk + (t4 << 1)];
                a1f[1] = *(const unsigned*)&As1[mr + g + 8][kk + (t4 << 1)];
                a1f[2] = *(const unsigned*)&As1[mr + g][kk + 8 + (t4 << 1)];
                a1f[3] = *(const unsigned*)&As1[mr + g + 8][kk + 8 + (t4 << 1)];
                a2f[0] = *(const unsigned*)&As2[mr + g][kk + (t4 << 1)];
                a2f[1] = *(const unsigned*)&As2[mr + g + 8][kk + (t4 << 1)];
                a2f[2] = *(const unsigned*)&As2[mr + g][kk + 8 + (t4 << 1)];
                a2f[3] = *(const unsigned*)&As2[mr + g + 8][kk + 8 + (t4 << 1)];
#pragma unroll
                for (int nt = 0; nt < 4; nt++) {
                    MMA_BF16(acc[mt][nt], a1f, b1f[nt]);
                    MMA_BF16(acc[mt][nt], a1f, b2f[nt]);
                    MMA_BF16(acc[mt][nt], a2f, b1f[nt]);
                }
            }
        }
    }

    // epilogue: scatter into g_xproj[((d*256+s)*1024+g)*16+b] with bias
#pragma unroll
    for (int mt = 0; mt < 4; mt++) {
#pragma unroll
        for (int nt = 0; nt < 4; nt++) {
            int mA = m0 + (wm << 6) + (mt << 4) + g;
            int nA = n0 + (wn << 5) + (nt << 3) + (t4 << 1);
            const float* c = acc[mt][nt];
#pragma unroll
            for (int e = 0; e < 4; e++) {
                int m = mA + ((e >> 1) << 3);
                int n = nA + (e & 1);
                int s = m >> 4, b = m & 15;
                int d = n >> 10, gg = n & 1023;
                g_xproj[(size_t)((((d << 8) | s) << 10) | gg) * BATCH + b] =
                    c[e] + __ldg(&bias[n]);
            }
        }
    }
}

// ---------------- 3) LSTM recurrence: cluster(8) + DSMEM ---------------------
// CTA = (dir bx>>6, bgroup (bx>>3)&7 [2 batches], rank bx&7 [32 units]).
// R12: 8 arrivals (1 publisher thread per dst, both halves), 256-thread reduce.
__global__ __launch_bounds__(256) __cluster_dims__(8, 1, 1)
void lstm_rec_kernel(int layer, const float* __restrict__ whh) {
    float* __restrict__ xout = layer ? g_xa : g_xb;
    int bx  = blockIdx.x;
    int dir = bx >> 6;
    int bgp = (bx >> 3) & 7;           // batches b0 = bgp*2, +1
    int rk  = bx & 7;                  // unit group: units j0..j0+31
    int j0  = rk << 5;
    int b0  = bgp << 1;
    int tid = threadIdx.x;
    int ks  = tid >> 5;                // k-slice 0..7 (32 k each)
    int un  = tid & 31;                // unit within group

    __shared__ __align__(16) float h_buf[2][512];     // [buf][b*256 + unit]
    __shared__ __align__(16) float part_s[8][264];    // [ks][gate g]
    __shared__ __align__(16) float gate_s[256];       // [q*64 + u*2 + b]
    __shared__ __align__(16) float hstage[64];        // [b*32 + u]
    __shared__ __align__(8)  unsigned long long mbar_store;

    unsigned sm_h    = smem_u32(&h_buf[0][0]);
    unsigned sm_mbar = smem_u32(&mbar_store);

    unsigned long long w_ull[4][16];
#pragma unroll
    for (int q = 0; q < 4; q++) {
        const float* wr = whh + (size_t)((dir << 10) + (q << 8) + j0 + un) * HID + (ks << 5);
#pragma unroll
        for (int m = 0; m < 8; m++) {
            float4 f = *(const float4*)&wr[m << 2];
            w_ull[q][m * 2]     = pack2(f.x, f.y);
            w_ull[q][m * 2 + 1] = pack2(f.z, f.w);
        }
    }
    if (tid < 128) *(float4*)&h_buf[0][tid << 2] = make_float4(0.f, 0.f, 0.f, 0.f);
    if (tid == 0) mbar_init(sm_mbar, 8u);
    __syncthreads();
    asm volatile("barrier.cluster.arrive.aligned;" ::: "memory");
    asm volatile("barrier.cluster.wait.aligned;"   ::: "memory");

    float c_reg = 0.f;                 // act threads tid<64: u = tid>>1, b = tid&1
    int au = tid >> 1, ab = tid & 1;
    // per-thread gate mapping (reduce): q = tid>>6, u = (tid&63)>>1, b = tid&1
    int rd_q = tid >> 6, rd_u = (tid & 63) >> 1, rd_b = tid & 1;
    int xpb = (dir << 22) + ((rd_q << 8) + j0 + rd_u) * BATCH + b0 + rd_b;

    for (int p = 0; p < SQ; p++) {
        int t = dir ? (SQ - 1 - p) : p;
        float xp = __ldg(&g_xproj[xpb + (t << 14)]);   // overlaps wait
        if (p > 0) mbar_wait(sm_mbar, (unsigned)((p - 1) & 1));

        const float* hcur = &h_buf[p & 1][0];
        unsigned long long acc[4][2];
#pragma unroll
        for (int q = 0; q < 4; q++) { acc[q][0] = 0ull; acc[q][1] = 0ull; }
#pragma unroll
        for (int b = 0; b < 2; b++) {
            const float* hb = hcur + (b << 8) + (ks << 5);
#pragma unroll
            for (int m = 0; m < 8; m++) {
                float4 h4 = *(const float4*)&hb[m << 2];
                unsigned long long h01 = pack2(h4.x, h4.y);
                unsigned long long h23 = pack2(h4.z, h4.w);
#pragma unroll
                for (int q = 0; q < 4; q++) {
                    acc[q][b] = ffma2(w_ull[q][m * 2],     h01, acc[q][b]);
                    acc[q][b] = ffma2(w_ull[q][m * 2 + 1], h23, acc[q][b]);
                }
            }
        }
#pragma unroll
        for (int q = 0; q < 4; q++) {
            float2 s0 = unpack2(acc[q][0]);
            float2 s1 = unpack2(acc[q][1]);
            *(float2*)&part_s[ks][(q << 6) + (un << 1)] =
                make_float2(s0.x + s0.y, s1.x + s1.y);
        }
        __syncthreads();

        // 256-thread reduce: thread t owns gate t
        {
            float gsum = xp;
#pragma unroll
            for (int s2 = 0; s2 < 8; s2++) gsum += part_s[s2][tid];
            gate_s[tid] = gsum;
        }
        __syncthreads();

        if (tid < 64) {
            float g0 = gate_s[tid];
            float g1 = gate_s[64 + tid];
            float g2 = gate_s[128 + tid];
            float g3 = gate_s[192 + tid];
            c_reg = fsig(g1) * c_reg + fsig(g0) * ftanh(g2);
            float h = fsig(g3) * ftanh(c_reg);
            hstage[(ab << 5) + au] = h;
            xout[(size_t)((t * BATCH + b0 + ab) << 9) + (dir << 8) + j0 + au] = h;
            asm volatile("bar.sync 1, 64;" ::: "memory");
            // publishers: thread d (0..7) sends both halves to dst d + 1 arrive
            if (p + 1 < SQ && tid < 8) {
                unsigned dst = (unsigned)tid;
                unsigned off = sm_h + (((p + 1) & 1) << 11) + (j0 << 2);
                unsigned ra0 = mapa_u32(off, dst);           // b = 0
                unsigned ra1 = mapa_u32(off + 1024u, dst);   // b = 1
                const float4* s0 = (const float4*)&hstage[0];
                const float4* s1 = (const float4*)&hstage[32];
#pragma unroll
                for (int i = 0; i < 8; i++) st_cluster_v4(ra0 + (i << 4), s0[i]);
#pragma unroll
                for (int i = 0; i < 8; i++) st_cluster_v4(ra1 + (i << 4), s1[i]);
                mbar_arrive_rank(sm_mbar, dst);
            }
        }
    }
    asm volatile("barrier.cluster.arrive.aligned;" ::: "memory");
    asm volatile("barrier.cluster.wait.aligned;"   ::: "memory");
}

// ---------------- 4) attention projections ----------------------------------
__global__ __launch_bounds__(256) void attnproj_kernel(const float* __restrict__ Ua,
                                                       const float* __restrict__ Wa) {
    const float* __restrict__ A = g_xa;   // layer-1 output [s][b][512]
    __shared__ __align__(16) float As[16][68];
    __shared__ __align__(16) float Bs[16][68];
    int m0 = blockIdx.y << 6;
    int n0 = blockIdx.x << 6;
    const float* Wsel = (n0 < 128) ? Ua : Wa;
    int nbase = (n0 < 128) ? n0 : (n0 - 128);
    float* out = (n0 < 128) ? g_p : g_cq;

    int tid = threadIdx.x;
    int tm = tid >> 4, tn = tid & 15;
    int lr = tid >> 2, lc = (tid & 3) << 2;

    unsigned long long accp[4][2];
#pragma unroll
    for (int i = 0; i < 4; i++) { accp[i][0] = 0ull; accp[i][1] = 0ull; }

    for (int k0 = 0; k0 < INW; k0 += 16) {
        float4 av = *(const float4*)&A[(size_t)(m0 + lr) * INW + k0 + lc];
        float4 bv = *(const float4*)&Wsel[(size_t)(nbase + lr) * INW + k0 + lc];
        As[lc + 0][lr] = av.x; As[lc + 1][lr] = av.y; As[lc + 2][lr] = av.z; As[lc + 3][lr] = av.w;
        Bs[lc + 0][lr] = bv.x; Bs[lc + 1][lr] = bv.y; Bs[lc + 2][lr] = bv.z; Bs[lc + 3][lr] = bv.w;
        __syncthreads();
#pragma unroll
        for (int kk = 0; kk < 16; kk++) {
            float4 a4 = *(const float4*)&As[kk][tm << 2];
            ulonglong2 b2 = *(const ulonglong2*)&Bs[kk][tn << 2];
            unsigned long long ad0 = pack2(a4.x, a4.x);
            unsigned long long ad1 = pack2(a4.y, a4.y);
            unsigned long long ad2 = pack2(a4.z, a4.z);
            unsigned long long ad3 = pack2(a4.w, a4.w);
            accp[0][0] = ffma2(ad0, b2.x, accp[0][0]);
            accp[0][1] = ffma2(ad0, b2.y, accp[0][1]);
            accp[1][0] = ffma2(ad1, b2.x, accp[1][0]);
            accp[1][1] = ffma2(ad1, b2.y, accp[1][1]);
            accp[2][0] = ffma2(ad2, b2.x, accp[2][0]);
            accp[2][1] = ffma2(ad2, b2.y, accp[2][1]);
            accp[3][0] = ffma2(ad3, b2.x, accp[3][0]);
            accp[3][1] = ffma2(ad3, b2.y, accp[3][1]);
        }
        __syncthreads();
    }
#pragma unroll
    for (int i = 0; i < 4; i++) {
        int m = m0 + (tm << 2) + i;
        int s = m >> 4, b = m & 15;
        float2 u0 = unpack2(accp[i][0]);
        float2 u1 = unpack2(accp[i][1]);
        float vals[4] = {u0.x, u0.y, u1.x, u1.y};
#pragma unroll
        for (int j = 0; j < 4; j++) {
            int nl = nbase + (tn << 2) + j;
            out[(size_t)(((b << 8) + s) << 7) + nl] = vals[j];
        }
    }
}

// ---------------- 5) pairwise scores + predictions --------------------------
__global__ __launch_bounds__(256) void scores_kernel(const float* __restrict__ va,
                                                     float* __restrict__ out,
                                                     int write_pred) {
    __shared__ __align__(16) float ps[32][132];
    __shared__ __align__(16) float cs[32][132];
    __shared__ float va_s[HMD];
    int b  = blockIdx.z;
    int i0 = blockIdx.y << 5, j0 = blockIdx.x << 5;
    int tid = threadIdx.x;
    if (tid < HMD) va_s[tid] = va[tid];
#pragma unroll
    for (int i = 0; i < 4; i++) {
        int f4 = tid + (i << 8);
        int row = f4 >> 5;
        int col = (f4 & 31) << 2;
        *(float4*)&ps[row][col] =
            *(const float4*)&g_p[(size_t)(((b << 8) + i0 + row) << 7) + col];
        *(float4*)&cs[row][col] =
            *(const float4*)&g_cq[(size_t)(((b << 8) + j0 + row) << 7) + col];
    }
    __syncthreads();

    int tj = tid & 15, ti = tid >> 4;
    int ia = ti << 1, ja = tj << 1;
    float s00 = 0.f, s01 = 0.f, s10 = 0.f, s11 = 0.f;
#pragma unroll 4
    for (int h = 0; h < HMD; h++) {
        float v  = va_s[h];
        float pa = ps[ia][h],     pb = ps[ia + 1][h];
        float ca = cs[ja][h],     cb = cs[ja + 1][h];
        s00 += v * ftanh(pa + ca);
        s01 += v * ftanh(pa + cb);
        s10 += v * ftanh(pb + ca);
        s11 += v * ftanh(pb + cb);
    }
    int gi = i0 + ia, gj = j0 + ja;
    size_t base = ((size_t)b << 16) + ((size_t)gi << 8) + gj;
    out[base]           = s00;
    out[base + 1]       = s01;
    out[base + 256]     = s10;
    out[base + 257]     = s11;
    if (write_pred) {
        float* po = out + NSC;
        po[base]       = (s00 >= 0.f) ? 1.f : 0.f;
        po[base + 1]   = (s01 >= 0.f) ? 1.f : 0.f;
        po[base + 256] = (s10 >= 0.f) ? 1.f : 0.f;
        po[base + 257] = (s11 >= 0.f) ? 1.f : 0.f;
    }
}

// ---------------- launch -----------------------------------------------------
extern "C" void kernel_launch(void* const* d_in, const int* in_sizes, int n_in,
                              void* d_out, int out_size) {
    const int*   concepts = (const int*)d_in[0];
    const float* emb  = (const float*)d_in[2];
    const float* w_ih = (const float*)d_in[3];
    const float* w_hh = (const float*)d_in[4];
    const float* bias = (const float*)d_in[5];
    const float* Ua   = (const float*)d_in[6];
    const float* Wa   = (const float*)d_in[7];
    const float* va   = (const float*)d_in[8];
    float* out = (float*)d_out;

    float* d_xa; float* d_xb;
    cudaGetSymbolAddress((void**)&d_xa, g_xa);
    cudaGetSymbolAddress((void**)&d_xb, g_xb);
    uint2 *d_a1, *d_a2, *d_w1, *d_w2;
    cudaGetSymbolAddress((void**)&d_a1, g_a1);
    cudaGetSymbolAddress((void**)&d_a2, g_a2);
    cudaGetSymbolAddress((void**)&d_w1, g_w1);
    cudaGetSymbolAddress((void**)&d_w2, g_w2);

    noop_kernel<<<1, 32>>>();                                          // #1
    embed_kernel<<<NROWS, 128>>>(concepts, emb);                       // #2

    // layer 0
    split_kernel<<<1024, 256>>>((const float4*)d_xa, d_a1, d_a2, NROWS * EMB / 4);   // #3
    split_kernel<<<512, 256>>>((const float4*)w_ih, d_w1, d_w2, 2 * G4 * EMB / 4);   // #4
    inproj_mma_kernel<<<dim3(16, 32), 256>>>(bias);                    // #5
    lstm_rec_kernel<<<128, 256>>>(0, w_hh);                            // #6 <- ncu

    // layer 1
    split_kernel<<<1024, 256>>>((const float4*)d_xb, d_a1, d_a2, NROWS * EMB / 4);
    split_kernel<<<512, 256>>>((const float4*)(w_ih + 2 * G4 * EMB), d_w1, d_w2,
                               2 * G4 * EMB / 4);
    inproj_mma_kernel<<<dim3(16, 32), 256>>>(bias + 2 * G4);
    lstm_rec_kernel<<<128, 256>>>(1, w_hh + 2 * G4 * HID);

    attnproj_kernel<<<dim3(4, 64), 256>>>(Ua, Wa);

    int write_pred = (out_size >= 2 * NSC) ? 1 : 0;
    scores_kernel<<<dim3(8, 8, BATCH), 256>>>(va, out, write_pred);
}

// round 14
// speedup vs baseline: 1.0573x; 1.0573x over previous
#include <cuda_runtime.h>
#include <cuda_bf16.h>

#define SQ    256
#define BATCH 16
#define EMB   512
#define HID   256
#define HMD   128
#define G4    1024            // 4*HID
#define NROWS (SQ*BATCH)      // 4096
#define INW   512             // input width both layers (E = 2H = 512)
#define NSC   (BATCH*SQ*SQ)   // 1,048,576 scores

// ---------------- scratch (device globals; no allocations allowed) ----------
__device__ float g_xa[NROWS * EMB];                 // 8 MB
__device__ float g_xb[NROWS * EMB];                 // 8 MB
__device__ float g_xproj[2 * SQ * G4 * BATCH];      // 32 MB : [dir][t][gate(1024)][b]
__device__ float g_p[BATCH * SQ * HMD];             // 2 MB
__device__ float g_cq[BATCH * SQ * HMD];            // 2 MB
// bf16 split operands (hi/lo)
__device__ uint2 g_a1[NROWS * EMB / 4];             // 4 MB (split of current GEMM input)
__device__ uint2 g_a2[NROWS * EMB / 4];             // 4 MB
__device__ uint2 g_w1[2 * 2 * G4 * EMB / 4];        // 4 MB (w_ih both layers, bf16 hi)
__device__ uint2 g_w2[2 * 2 * G4 * EMB / 4];        // 4 MB (lo)
__device__ uint2 g_u1[2 * HMD * INW / 4];           // 256 KB ([Ua;Wa] hi)
__device__ uint2 g_u2[2 * HMD * INW / 4];           // 256 KB (lo)

// ---------------- f32x2 packed math ------------------------------------------
__device__ __forceinline__ unsigned long long ffma2(unsigned long long a,
                                                    unsigned long long b,
                                                    unsigned long long c) {
    unsigned long long d;
    asm("fma.rn.f32x2 %0, %1, %2, %3;" : "=l"(d) : "l"(a), "l"(b), "l"(c));
    return d;
}
__device__ __forceinline__ unsigned long long pack2(float x, float y) {
    unsigned long long d;
    asm("mov.b64 %0, {%1, %2};" : "=l"(d) : "f"(x), "f"(y));
    return d;
}
__device__ __forceinline__ float2 unpack2(unsigned long long v) {
    float2 r;
    asm("mov.b64 {%0, %1}, %2;" : "=f"(r.x), "=f"(r.y) : "l"(v));
    return r;
}

// ---------------- cluster / mbarrier helpers ---------------------------------
__device__ __forceinline__ unsigned smem_u32(const void* p) {
    unsigned a;
    asm("{ .reg .u64 t; cvta.to.shared.u64 t, %1; cvt.u32.u64 %0, t; }"
        : "=r"(a) : "l"(p));
    return a;
}
__device__ __forceinline__ unsigned mapa_u32(unsigned addr, unsigned rank) {
    unsigned r;
    asm("mapa.shared::cluster.u32 %0, %1, %2;" : "=r"(r) : "r"(addr), "r"(rank));
    return r;
}
__device__ __forceinline__ void st_cluster_v4(unsigned addr, float4 v) {
    asm volatile("st.shared::cluster.v4.f32 [%0], {%1, %2, %3, %4};"
                 :: "r"(addr), "f"(v.x), "f"(v.y), "f"(v.z), "f"(v.w) : "memory");
}
__device__ __forceinline__ void mbar_init(unsigned addr, unsigned cnt) {
    asm volatile("mbarrier.init.shared.b64 [%0], %1;" :: "r"(addr), "r"(cnt) : "memory");
}
__device__ __forceinline__ void mbar_arrive_rank(unsigned local_mbar, unsigned rank) {
    asm volatile(
        "{ .reg .b32 ra; mapa.shared::cluster.u32 ra, %0, %1;\n\t"
        "mbarrier.arrive.release.cluster.shared::cluster.b64 _, [ra]; }"
        :: "r"(local_mbar), "r"(rank) : "memory");
}
__device__ __forceinline__ void mbar_wait(unsigned mbar, unsigned parity) {
    unsigned done = 0;
    while (!done) {
        asm volatile(
            "{ .reg .pred p;\n\t"
            "mbarrier.try_wait.parity.acquire.cluster.shared::cta.b64 p, [%1], %2, 0x989680;\n\t"
            "selp.b32 %0, 1, 0, p; }"
            : "=r"(done) : "r"(mbar), "r"(parity) : "memory");
    }
}

// ---------------- bf16 split helpers ------------------------------------------
__device__ __forceinline__ void split4(float4 v, uint2& hi, uint2& lo) {
    __nv_bfloat16 a0 = __float2bfloat16(v.x), a1 = __float2bfloat16(v.y);
    __nv_bfloat16 a2 = __float2bfloat16(v.z), a3 = __float2bfloat16(v.w);
    float r0 = v.x - __bfloat162float(a0), r1 = v.y - __bfloat162float(a1);
    float r2 = v.z - __bfloat162float(a2), r3 = v.w - __bfloat162float(a3);
    __nv_bfloat16 b0 = __float2bfloat16(r0), b1 = __float2bfloat16(r1);
    __nv_bfloat16 b2 = __float2bfloat16(r2), b3 = __float2bfloat16(r3);
    hi.x = ((unsigned)__bfloat16_as_ushort(a1) << 16) | __bfloat16_as_ushort(a0);
    hi.y = ((unsigned)__bfloat16_as_ushort(a3) << 16) | __bfloat16_as_ushort(a2);
    lo.x = ((unsigned)__bfloat16_as_ushort(b1) << 16) | __bfloat16_as_ushort(b0);
    lo.y = ((unsigned)__bfloat16_as_ushort(b3) << 16) | __bfloat16_as_ushort(b2);
}
__device__ __forceinline__ void split1(float v, unsigned short& hi, unsigned short& lo) {
    __nv_bfloat16 h = __float2bfloat16(v);
    float r = v - __bfloat162float(h);
    hi = __bfloat16_as_ushort(h);
    lo = __bfloat16_as_ushort(__float2bfloat16(r));
}

// ---------------- scalar math helpers ----------------------------------------
__device__ __forceinline__ float ftanh(float x) {
    x = fminf(fmaxf(x, -15.f), 15.f);
    float e = __expf(2.f * x);
    return 1.f - __fdividef(2.f, e + 1.f);
}
__device__ __forceinline__ float fsig(float x) {
    x = fminf(fmaxf(x, -30.f), 30.f);
    return __fdividef(1.f, 1.f + __expf(-x));
}

// ---------------- 0) noop ------------------------------------------------------
__global__ void noop_kernel() {}

// ---------------- 1) embedding gather + inline bf16 split --------------------
__global__ __launch_bounds__(128) void embed_kernel(const int* __restrict__ concepts,
                                                    const float* __restrict__ emb) {
    int row = blockIdx.x;                       // s*16 + b
    int tok = concepts[row];
    const float4* src = (const float4*)(emb + (size_t)tok * EMB);
    float4 v = src[threadIdx.x];
    ((float4*)(g_xa + (size_t)row * EMB))[threadIdx.x] = v;
    uint2 h, l;
    split4(v, h, l);
    g_a1[row * 128 + threadIdx.x] = h;
    g_a2[row * 128 + threadIdx.x] = l;
}

// ---------------- 1b) fp32 -> bf16 hi/lo split (weights only) ----------------
__global__ __launch_bounds__(256) void split_kernel(const float4* __restrict__ src,
                                                    uint2* __restrict__ d1,
                                                    uint2* __restrict__ d2, int n4) {
    int stride = gridDim.x * blockDim.x;
    for (int i = blockIdx.x * blockDim.x + threadIdx.x; i < n4; i += stride) {
        float4 v = src[i];
        uint2 h, l;
        split4(v, h, l);
        d1[i] = h;
        d2[i] = l;
    }
}

// ---------------- 2) input projection via mma.sync bf16x3 --------------------
#define MMA_BF16(c, a, b)                                                       \
    asm volatile(                                                               \
        "mma.sync.aligned.m16n8k16.row.col.f32.bf16.bf16.f32 "                  \
        "{%0,%1,%2,%3}, {%4,%5,%6,%7}, {%8,%9}, {%0,%1,%2,%3};"                 \
        : "+f"((c)[0]), "+f"((c)[1]), "+f"((c)[2]), "+f"((c)[3])                \
        : "r"((a)[0]), "r"((a)[1]), "r"((a)[2]), "r"((a)[3]),                   \
          "r"((b)[0]), "r"((b)[1]))

__global__ __launch_bounds__(256, 2) void inproj_mma_kernel(int layer,
                                                            const float* __restrict__ bias) {
    __shared__ __align__(16) unsigned short As1[128][40];
    __shared__ __align__(16) unsigned short As2[128][40];
    __shared__ __align__(16) unsigned short Ws1[128][40];
    __shared__ __align__(16) unsigned short Ws2[128][40];
    int tid = threadIdx.x, wid = tid >> 5, lane = tid & 31;
    int n0 = blockIdx.x << 7, m0 = blockIdx.y << 7;
    int wm = wid >> 2, wn = wid & 3;
    int g = lane >> 2, t4 = lane & 3;

    const uint4* A1 = (const uint4*)g_a1;
    const uint4* A2 = (const uint4*)g_a2;
    const uint4* W1 = (const uint4*)g_w1 + (size_t)layer * 131072;
    const uint4* W2 = (const uint4*)g_w2 + (size_t)layer * 131072;

    float acc[4][4][4];
#pragma unroll
    for (int mt = 0; mt < 4; mt++)
#pragma unroll
        for (int nt = 0; nt < 4; nt++)
#pragma unroll
            for (int i = 0; i < 4; i++) acc[mt][nt][i] = 0.f;

    for (int ch = 0; ch < 16; ch++) {
        int kb = (ch << 2);
        uint4 ra1[2], ra2[2], rw1[2], rw2[2];
        int r0 = (tid * 2) >> 2, c0 = (tid * 2) & 3;
        int r1 = (tid * 2 + 1) >> 2, c1 = (tid * 2 + 1) & 3;
        ra1[0] = A1[(size_t)(m0 + r0) * 64 + kb + c0];
        ra1[1] = A1[(size_t)(m0 + r1) * 64 + kb + c1];
        ra2[0] = A2[(size_t)(m0 + r0) * 64 + kb + c0];
        ra2[1] = A2[(size_t)(m0 + r1) * 64 + kb + c1];
        rw1[0] = W1[(size_t)(n0 + r0) * 64 + kb + c0];
        rw1[1] = W1[(size_t)(n0 + r1) * 64 + kb + c1];
        rw2[0] = W2[(size_t)(n0 + r0) * 64 + kb + c0];
        rw2[1] = W2[(size_t)(n0 + r1) * 64 + kb + c1];
        __syncthreads();
        *(uint4*)&As1[r0][c0 << 3] = ra1[0];
        *(uint4*)&As1[r1][c1 << 3] = ra1[1];
        *(uint4*)&As2[r0][c0 << 3] = ra2[0];
        *(uint4*)&As2[r1][c1 << 3] = ra2[1];
        *(uint4*)&Ws1[r0][c0 << 3] = rw1[0];
        *(uint4*)&Ws1[r1][c1 << 3] = rw1[1];
        *(uint4*)&Ws2[r0][c0 << 3] = rw2[0];
        *(uint4*)&Ws2[r1][c1 << 3] = rw2[1];
        __syncthreads();

#pragma unroll
        for (int k16 = 0; k16 < 2; k16++) {
            int kk = k16 << 4;
            unsigned b1f[4][2], b2f[4][2];
#pragma unroll
            for (int nt = 0; nt < 4; nt++) {
                int nr = (wn << 5) + (nt << 3) + g;
                b1f[nt][0] = *(const unsigned*)&Ws1[nr][kk + (t4 << 1)];
                b1f[nt][1] = *(const unsigned*)&Ws1[nr][kk + 8 + (t4 << 1)];
                b2f[nt][0] = *(const unsigned*)&Ws2[nr][kk + (t4 << 1)];
                b2f[nt][1] = *(const unsigned*)&Ws2[nr][kk + 8 + (t4 << 1)];
            }
#pragma unroll
            for (int mt = 0; mt < 4; mt++) {
                int mr = (wm << 6) + (mt << 4);
                unsigned a1f[4], a2f[4];
                a1f[0] = *(const unsigned*)&As1[mr + g][kk + (t4 << 1)];
                a1f[1] = *(const unsigned*)&As1[mr + g + 8][kk + (t4 << 1)];
                a1f[2] = *(const unsigned*)&As1[mr + g][kk + 8 + (t4 << 1)];
                a1f[3] = *(const unsigned*)&As1[mr + g + 8][kk + 8 + (t4 << 1)];
                a2f[0] = *(const unsigned*)&As2[mr + g][kk + (t4 << 1)];
                a2f[1] = *(const unsigned*)&As2[mr + g + 8][kk + (t4 << 1)];
                a2f[2] = *(const unsigned*)&As2[mr + g][kk + 8 + (t4 << 1)];
                a2f[3] = *(const unsigned*)&As2[mr + g + 8][kk + 8 + (t4 << 1)];
#pragma unroll
                for (int nt = 0; nt < 4; nt++) {
                    MMA_BF16(acc[mt][nt], a1f, b1f[nt]);
                    MMA_BF16(acc[mt][nt], a1f, b2f[nt]);
                    MMA_BF16(acc[mt][nt], a2f, b1f[nt]);
                }
            }
        }
    }

#pragma unroll
    for (int mt = 0; mt < 4; mt++) {
#pragma unroll
        for (int nt = 0; nt < 4; nt++) {
            int mA = m0 + (wm << 6) + (mt << 4) + g;
            int nA = n0 + (wn << 5) + (nt << 3) + (t4 << 1);
            const float* c = acc[mt][nt];
#pragma unroll
            for (int e = 0; e < 4; e++) {
                int m = mA + ((e >> 1) << 3);
                int n = nA + (e & 1);
                int s = m >> 4, b = m & 15;
                int d = n >> 10, gg = n & 1023;
                g_xproj[(size_t)((((d << 8) | s) << 10) | gg) * BATCH + b] =
                    c[e] + __ldg(&bias[n]);
            }
        }
    }
}

// ---------------- 2b) attention projections via mma.sync bf16x3 --------------
// [4096,512] x [256,512]^T ; rows 0-127 of W = Ua -> g_p, 128-255 = Wa -> g_cq.
__global__ __launch_bounds__(256, 2) void attn_mma_kernel() {
    __shared__ __align__(16) unsigned short As1[128][40];
    __shared__ __align__(16) unsigned short As2[128][40];
    __shared__ __align__(16) unsigned short Ws1[128][40];
    __shared__ __align__(16) unsigned short Ws2[128][40];
    int tid = threadIdx.x, wid = tid >> 5, lane = tid & 31;
    int n0 = blockIdx.x << 7, m0 = blockIdx.y << 7;   // n0 in {0,128}
    int wm = wid >> 2, wn = wid & 3;
    int g = lane >> 2, t4 = lane & 3;
    float* __restrict__ out = (blockIdx.x == 0) ? g_p : g_cq;

    const uint4* A1 = (const uint4*)g_a1;
    const uint4* A2 = (const uint4*)g_a2;
    const uint4* W1 = (const uint4*)g_u1;
    const uint4* W2 = (const uint4*)g_u2;

    float acc[4][4][4];
#pragma unroll
    for (int mt = 0; mt < 4; mt++)
#pragma unroll
        for (int nt = 0; nt < 4; nt++)
#pragma unroll
            for (int i = 0; i < 4; i++) acc[mt][nt][i] = 0.f;

    for (int ch = 0; ch < 16; ch++) {
        int kb = (ch << 2);
        uint4 ra1[2], ra2[2], rw1[2], rw2[2];
        int r0 = (tid * 2) >> 2, c0 = (tid * 2) & 3;
        int r1 = (tid * 2 + 1) >> 2, c1 = (tid * 2 + 1) & 3;
        ra1[0] = A1[(size_t)(m0 + r0) * 64 + kb + c0];
        ra1[1] = A1[(size_t)(m0 + r1) * 64 + kb + c1];
        ra2[0] = A2[(size_t)(m0 + r0) * 64 + kb + c0];
        ra2[1] = A2[(size_t)(m0 + r1) * 64 + kb + c1];
        rw1[0] = W1[(size_t)(n0 + r0) * 64 + kb + c0];
        rw1[1] = W1[(size_t)(n0 + r1) * 64 + kb + c1];
        rw2[0] = W2[(size_t)(n0 + r0) * 64 + kb + c0];
        rw2[1] = W2[(size_t)(n0 + r1) * 64 + kb + c1];
        __syncthreads();
        *(uint4*)&As1[r0][c0 << 3] = ra1[0];
        *(uint4*)&As1[r1][c1 << 3] = ra1[1];
        *(uint4*)&As2[r0][c0 << 3] = ra2[0];
        *(uint4*)&As2[r1][c1 << 3] = ra2[1];
        *(uint4*)&Ws1[r0][c0 << 3] = rw1[0];
        *(uint4*)&Ws1[r1][c1 << 3] = rw1[1];
        *(uint4*)&Ws2[r0][c0 << 3] = rw2[0];
        *(uint4*)&Ws2[r1][c1 << 3] = rw2[1];
        __syncthreads();

#pragma unroll
        for (int k16 = 0; k16 < 2; k16++) {
            int kk = k16 << 4;
            unsigned b1f[4][2], b2f[4][2];
#pragma unroll
            for (int nt = 0; nt < 4; nt++) {
                int nr = (wn << 5) + (nt << 3) + g;
                b1f[nt][0] = *(const unsigned*)&Ws1[nr][kk + (t4 << 1)];
                b1f[nt][1] = *(const unsigned*)&Ws1[nr][kk + 8 + (t4 << 1)];
                b2f[nt][0] = *(const unsigned*)&Ws2[nr][kk + (t4 << 1)];
                b2f[nt][1] = *(const unsigned*)&Ws2[nr][kk + 8 + (t4 << 1)];
            }
#pragma unroll
            for (int mt = 0; mt < 4; mt++) {
                int mr = (wm << 6) + (mt << 4);
                unsigned a1f[4], a2f[4];
                a1f[0] = *(const unsigned*)&As1[mr + g][kk + (t4 << 1)];
                a1f[1] = *(const unsigned*)&As1[mr + g + 8][kk + (t4 << 1)];
                a1f[2] = *(const unsigned*)&As1[mr + g][kk + 8 + (t4 << 1)];
                a1f[3] = *(const unsigned*)&As1[mr + g + 8][kk + 8 + (t4 << 1)];
                a2f[0] = *(const unsigned*)&As2[mr + g][kk + (t4 << 1)];
                a2f[1] = *(const unsigned*)&As2[mr + g + 8][kk + (t4 << 1)];
                a2f[2] = *(const unsigned*)&As2[mr + g][kk + 8 + (t4 << 1)];
                a2f[3] = *(const unsigned*)&As2[mr + g + 8][kk + 8 + (t4 << 1)];
#pragma unroll
                for (int nt = 0; nt < 4; nt++) {
                    MMA_BF16(acc[mt][nt], a1f, b1f[nt]);
                    MMA_BF16(acc[mt][nt], a1f, b2f[nt]);
                    MMA_BF16(acc[mt][nt], a2f, b1f[nt]);
                }
            }
        }
    }

#pragma unroll
    for (int mt = 0; mt < 4; mt++) {
#pragma unroll
        for (int nt = 0; nt < 4; nt++) {
            int mA = m0 + (wm << 6) + (mt << 4) + g;
            int nA = (wn << 5) + (nt << 3) + (t4 << 1);   // local col 0..127
            const float* c = acc[mt][nt];
#pragma unroll
            for (int e = 0; e < 4; e++) {
                int m = mA + ((e >> 1) << 3);
                int nl = nA + (e & 1);
                int s = m >> 4, b = m & 15;
                out[(size_t)(((b << 8) + s) << 7) + nl] = c[e];
            }
        }
    }
}

// ---------------- 3) LSTM recurrence: cluster(8) + DSMEM (R11-exact) ---------
// + inline bf16 split of xout in the act threads.
__global__ __launch_bounds__(256) __cluster_dims__(8, 1, 1)
void lstm_rec_kernel(int layer, const float* __restrict__ whh) {
    float* __restrict__ xout = layer ? g_xa : g_xb;
    int bx  = blockIdx.x;
    int dir = bx >> 6;
    int bgp = (bx >> 3) & 7;           // batches b0 = bgp*2, +1
    int rk  = bx & 7;                  // unit group: units j0..j0+31
    int j0  = rk << 5;
    int b0  = bgp << 1;
    int tid = threadIdx.x;
    int ks  = tid >> 5;                // k-slice 0..7 (32 k each)
    int un  = tid & 31;                // unit within group

    __shared__ __align__(16) float h_buf[2][512];     // [buf][b*256 + unit]
    __shared__ __align__(16) float part_s[8][264];    // [ks][gate g]
    __shared__ __align__(16) float hstage[64];        // [b*32 + u]
    __shared__ __align__(8)  unsigned long long mbar_store;

    unsigned sm_h    = smem_u32(&h_buf[0][0]);
    unsigned sm_mbar = smem_u32(&mbar_store);

    unsigned long long w_ull[4][16];
#pragma unroll
    for (int q = 0; q < 4; q++) {
        const float* wr = whh + (size_t)((dir << 10) + (q << 8) + j0 + un) * HID + (ks << 5);
#pragma unroll
        for (int m = 0; m < 8; m++) {
            float4 f = *(const float4*)&wr[m << 2];
            w_ull[q][m * 2]     = pack2(f.x, f.y);
            w_ull[q][m * 2 + 1] = pack2(f.z, f.w);
        }
    }
    if (tid < 128) *(float4*)&h_buf[0][tid << 2] = make_float4(0.f, 0.f, 0.f, 0.f);
    if (tid == 0) mbar_init(sm_mbar, 16u);
    __syncthreads();
    asm volatile("barrier.cluster.arrive.aligned;" ::: "memory");
    asm volatile("barrier.cluster.wait.aligned;"   ::: "memory");

    float c_reg = 0.f;
    int au = tid >> 1, ab = tid & 1;
    int xb0 = (dir << 22) + (j0 + au) * BATCH + b0 + ab;
    int xb1 = xb0 + (1 << 8) * BATCH;
    int xb2 = xb0 + (2 << 8) * BATCH;
    int xb3 = xb0 + (3 << 8) * BATCH;

    unsigned short* a1u = (unsigned short*)g_a1;
    unsigned short* a2u = (unsigned short*)g_a2;

    for (int p = 0; p < SQ; p++) {
        int t = dir ? (SQ - 1 - p) : p;
        float x0 = 0.f, x1 = 0.f, x2 = 0.f, x3 = 0.f;
        if (tid < 64) {
            x0 = __ldg(&g_xproj[xb0 + (t << 14)]);
            x1 = __ldg(&g_xproj[xb1 + (t << 14)]);
            x2 = __ldg(&g_xproj[xb2 + (t << 14)]);
            x3 = __ldg(&g_xproj[xb3 + (t << 14)]);
        }
        if (p > 0) mbar_wait(sm_mbar, (unsigned)((p - 1) & 1));

        const float* hcur = &h_buf[p & 1][0];
        unsigned long long acc[4][2];
#pragma unroll
        for (int q = 0; q < 4; q++) { acc[q][0] = 0ull; acc[q][1] = 0ull; }
#pragma unroll
        for (int b = 0; b < 2; b++) {
            const float* hb = hcur + (b << 8) + (ks << 5);
#pragma unroll
            for (int m = 0; m < 8; m++) {
                float4 h4 = *(const float4*)&hb[m << 2];
                unsigned long long h01 = pack2(h4.x, h4.y);
                unsigned long long h23 = pack2(h4.z, h4.w);
#pragma unroll
                for (int q = 0; q < 4; q++) {
                    acc[q][b] = ffma2(w_ull[q][m * 2],     h01, acc[q][b]);
                    acc[q][b] = ffma2(w_ull[q][m * 2 + 1], h23, acc[q][b]);
                }
            }
        }
#pragma unroll
        for (int q = 0; q < 4; q++) {
            float2 s0 = unpack2(acc[q][0]);
            float2 s1 = unpack2(acc[q][1]);
            *(float2*)&part_s[ks][(q << 6) + (un << 1)] =
                make_float2(s0.x + s0.y, s1.x + s1.y);
        }
        __syncthreads();

        if (tid < 64) {
            float g0 = x0, g1 = x1, g2 = x2, g3 = x3;
#pragma unroll
            for (int s2 = 0; s2 < 8; s2++) {
                g0 += part_s[s2][tid];
                g1 += part_s[s2][64 + tid];
                g2 += part_s[s2][128 + tid];
                g3 += part_s[s2][192 + tid];
            }
            c_reg = fsig(g1) * c_reg + fsig(g0) * ftanh(g2);
            float h = fsig(g3) * ftanh(c_reg);
            hstage[(ab << 5) + au] = h;
            size_t xi = (size_t)((t * BATCH + b0 + ab) << 9) + (dir << 8) + j0 + au;
            xout[xi] = h;
            unsigned short hh, hl;
            split1(h, hh, hl);
            a1u[xi] = hh;
            a2u[xi] = hl;
            asm volatile("bar.sync 1, 64;" ::: "memory");
            if (p + 1 < SQ && tid < 16) {
                unsigned dst = (unsigned)(tid >> 1);
                int b = tid & 1;
                unsigned off = sm_h + (((p + 1) & 1) << 11) + (b << 10) + (j0 << 2);
                unsigned ra = mapa_u32(off, dst);
                const float4* src = (const float4*)&hstage[b << 5];
#pragma unroll
                for (int i = 0; i < 8; i++) st_cluster_v4(ra + (i << 4), src[i]);
                mbar_arrive_rank(sm_mbar, dst);
            }
        }
    }
    asm volatile("barrier.cluster.arrive.aligned;" ::: "memory");
    asm volatile("barrier.cluster.wait.aligned;"   ::: "memory");
}

// ---------------- 5) pairwise scores + predictions --------------------------
__global__ __launch_bounds__(256) void scores_kernel(const float* __restrict__ va,
                                                     float* __restrict__ out,
                                                     int write_pred) {
    __shared__ __align__(16) float ps[32][132];
    __shared__ __align__(16) float cs[32][132];
    __shared__ float va_s[HMD];
    int b  = blockIdx.z;
    int i0 = blockIdx.y << 5, j0 = blockIdx.x << 5;
    int tid = threadIdx.x;
    if (tid < HMD) va_s[tid] = va[tid];
#pragma unroll
    for (int i = 0; i < 4; i++) {
        int f4 = tid + (i << 8);
        int row = f4 >> 5;
        int col = (f4 & 31) << 2;
        *(float4*)&ps[row][col] =
            *(const float4*)&g_p[(size_t)(((b << 8) + i0 + row) << 7) + col];
        *(float4*)&cs[row][col] =
            *(const float4*)&g_cq[(size_t)(((b << 8) + j0 + row) << 7) + col];
    }
    __syncthreads();

    int tj = tid & 15, ti = tid >> 4;
    int ia = ti << 1, ja = tj << 1;
    float s00 = 0.f, s01 = 0.f, s10 = 0.f, s11 = 0.f;
#pragma unroll 4
    for (int h = 0; h < HMD; h++) {
        float v  = va_s[h];
        float pa = ps[ia][h],     pb = ps[ia + 1][h];
        float ca = cs[ja][h],     cb = cs[ja + 1][h];
        s00 += v * ftanh(pa + ca);
        s01 += v * ftanh(pa + cb);
        s10 += v * ftanh(pb + ca);
        s11 += v * ftanh(pb + cb);
    }
    int gi = i0 + ia, gj = j0 + ja;
    size_t base = ((size_t)b << 16) + ((size_t)gi << 8) + gj;
    out[base]           = s00;
    out[base + 1]       = s01;
    out[base + 256]     = s10;
    out[base + 257]     = s11;
    if (write_pred) {
        float* po = out + NSC;
        po[base]       = (s00 >= 0.f) ? 1.f : 0.f;
        po[base + 1]   = (s01 >= 0.f) ? 1.f : 0.f;
        po[base + 256] = (s10 >= 0.f) ? 1.f : 0.f;
        po[base + 257] = (s11 >= 0.f) ? 1.f : 0.f;
    }
}

// ---------------- launch -----------------------------------------------------
extern "C" void kernel_launch(void* const* d_in, const int* in_sizes, int n_in,
                              void* d_out, int out_size) {
    const int*   concepts = (const int*)d_in[0];
    const float* emb  = (const float*)d_in[2];
    const float* w_ih = (const float*)d_in[3];
    const float* w_hh = (const float*)d_in[4];
    const float* bias = (const float*)d_in[5];
    const float* Ua   = (const float*)d_in[6];
    const float* Wa   = (const float*)d_in[7];
    const float* va   = (const float*)d_in[8];
    float* out = (float*)d_out;

    uint2 *d_w1, *d_w2, *d_u1, *d_u2;
    cudaGetSymbolAddress((void**)&d_w1, g_w1);
    cudaGetSymbolAddress((void**)&d_w2, g_w2);
    cudaGetSymbolAddress((void**)&d_u1, g_u1);
    cudaGetSymbolAddress((void**)&d_u2, g_u2);

    noop_kernel<<<1, 32>>>();                                          // #1
    embed_kernel<<<NROWS, 128>>>(concepts, emb);                       // #2 (+A split)

    // weight splits (input-constant)
    split_kernel<<<1024, 256>>>((const float4*)w_ih, d_w1, d_w2,
                                2 * 2 * G4 * EMB / 4);                 // #3
    split_kernel<<<64, 256>>>((const float4*)Ua, d_u1, d_u2,
                              HMD * INW / 4);                          // #4
    split_kernel<<<64, 256>>>((const float4*)Wa, d_u1 + HMD * INW / 4,
                              d_u2 + HMD * INW / 4, HMD * INW / 4);    // #5

    // layer 0
    inproj_mma_kernel<<<dim3(16, 32), 256>>>(0, bias);                 // #6
    lstm_rec_kernel<<<128, 256>>>(0, w_hh);                            // (+A split)
    // layer 1
    inproj_mma_kernel<<<dim3(16, 32), 256>>>(1, bias + 2 * G4);
    lstm_rec_kernel<<<128, 256>>>(1, w_hh + 2 * G4 * HID);             // (+A split)

    attn_mma_kernel<<<dim3(2, 32), 256>>>();

    int write_pred = (out_size >= 2 * NSC) ? 1 : 0;
    scores_kernel<<<dim3(8, 8, BATCH), 256>>>(va, out, write_pred);
}

// round 15
// speedup vs baseline: 1.0727x; 1.0145x over previous
#include <cuda_runtime.h>
#include <cuda_bf16.h>

#define SQ    256
#define BATCH 16
#define EMB   512
#define HID   256
#define HMD   128
#define G4    1024            // 4*HID
#define NROWS (SQ*BATCH)      // 4096
#define INW   512             // input width both layers (E = 2H = 512)
#define NSC   (BATCH*SQ*SQ)   // 1,048,576 scores

// ---------------- scratch (device globals; no allocations allowed) ----------
__device__ float g_xa[NROWS * EMB];                 // 8 MB
__device__ float g_xb[NROWS * EMB];                 // 8 MB
__device__ float g_xproj[2 * SQ * G4 * BATCH];      // 32 MB : [dir][t][gate(1024)][b]
__device__ float g_p[BATCH * SQ * HMD];             // 2 MB
__device__ float g_cq[BATCH * SQ * HMD];            // 2 MB
// bf16 split operands (hi/lo)
__device__ uint2 g_a1[NROWS * EMB / 4];             // 4 MB (split of current GEMM input)
__device__ uint2 g_a2[NROWS * EMB / 4];             // 4 MB
__device__ uint2 g_w1[2 * 2 * G4 * EMB / 4];        // 4 MB (w_ih both layers, bf16 hi)
__device__ uint2 g_w2[2 * 2 * G4 * EMB / 4];        // 4 MB (lo)
__device__ uint2 g_u1[2 * HMD * INW / 4];           // 256 KB ([Ua;Wa] hi)
__device__ uint2 g_u2[2 * HMD * INW / 4];           // 256 KB (lo)

// ---------------- f32x2 packed math ------------------------------------------
__device__ __forceinline__ unsigned long long ffma2(unsigned long long a,
                                                    unsigned long long b,
                                                    unsigned long long c) {
    unsigned long long d;
    asm("fma.rn.f32x2 %0, %1, %2, %3;" : "=l"(d) : "l"(a), "l"(b), "l"(c));
    return d;
}
__device__ __forceinline__ unsigned long long pack2(float x, float y) {
    unsigned long long d;
    asm("mov.b64 %0, {%1, %2};" : "=l"(d) : "f"(x), "f"(y));
    return d;
}
__device__ __forceinline__ float2 unpack2(unsigned long long v) {
    float2 r;
    asm("mov.b64 {%0, %1}, %2;" : "=f"(r.x), "=f"(r.y) : "l"(v));
    return r;
}

// ---------------- cluster / mbarrier helpers ---------------------------------
__device__ __forceinline__ unsigned smem_u32(const void* p) {
    unsigned a;
    asm("{ .reg .u64 t; cvta.to.shared.u64 t, %1; cvt.u32.u64 %0, t; }"
        : "=r"(a) : "l"(p));
    return a;
}
__device__ __forceinline__ unsigned mapa_u32(unsigned addr, unsigned rank) {
    unsigned r;
    asm("mapa.shared::cluster.u32 %0, %1, %2;" : "=r"(r) : "r"(addr), "r"(rank));
    return r;
}
__device__ __forceinline__ void st_cluster_v4(unsigned addr, float4 v) {
    asm volatile("st.shared::cluster.v4.f32 [%0], {%1, %2, %3, %4};"
                 :: "r"(addr), "f"(v.x), "f"(v.y), "f"(v.z), "f"(v.w) : "memory");
}
__device__ __forceinline__ void mbar_init(unsigned addr, unsigned cnt) {
    asm volatile("mbarrier.init.shared.b64 [%0], %1;" :: "r"(addr), "r"(cnt) : "memory");
}
__device__ __forceinline__ void mbar_arrive_rank(unsigned local_mbar, unsigned rank) {
    asm volatile(
        "{ .reg .b32 ra; mapa.shared::cluster.u32 ra, %0, %1;\n\t"
        "mbarrier.arrive.release.cluster.shared::cluster.b64 _, [ra]; }"
        :: "r"(local_mbar), "r"(rank) : "memory");
}
__device__ __forceinline__ void mbar_wait(unsigned mbar, unsigned parity) {
    unsigned done = 0;
    while (!done) {
        asm volatile(
            "{ .reg .pred p;\n\t"
            "mbarrier.try_wait.parity.acquire.cluster.shared::cta.b64 p, [%1], %2, 0x989680;\n\t"
            "selp.b32 %0, 1, 0, p; }"
            : "=r"(done) : "r"(mbar), "r"(parity) : "memory");
    }
}

// ---------------- bf16 split helpers ------------------------------------------
__device__ __forceinline__ void split4(float4 v, uint2& hi, uint2& lo) {
    __nv_bfloat16 a0 = __float2bfloat16(v.x), a1 = __float2bfloat16(v.y);
    __nv_bfloat16 a2 = __float2bfloat16(v.z), a3 = __float2bfloat16(v.w);
    float r0 = v.x - __bfloat162float(a0), r1 = v.y - __bfloat162float(a1);
    float r2 = v.z - __bfloat162float(a2), r3 = v.w - __bfloat162float(a3);
    __nv_bfloat16 b0 = __float2bfloat16(r0), b1 = __float2bfloat16(r1);
    __nv_bfloat16 b2 = __float2bfloat16(r2), b3 = __float2bfloat16(r3);
    hi.x = ((unsigned)__bfloat16_as_ushort(a1) << 16) | __bfloat16_as_ushort(a0);
    hi.y = ((unsigned)__bfloat16_as_ushort(a3) << 16) | __bfloat16_as_ushort(a2);
    lo.x = ((unsigned)__bfloat16_as_ushort(b1) << 16) | __bfloat16_as_ushort(b0);
    lo.y = ((unsigned)__bfloat16_as_ushort(b3) << 16) | __bfloat16_as_ushort(b2);
}
__device__ __forceinline__ void split1(float v, unsigned short& hi, unsigned short& lo) {
    __nv_bfloat16 h = __float2bfloat16(v);
    float r = v - __bfloat162float(h);
    hi = __bfloat16_as_ushort(h);
    lo = __bfloat16_as_ushort(__float2bfloat16(r));
}

// ---------------- scalar math helpers ----------------------------------------
__device__ __forceinline__ float ftanh(float x) {
    x = fminf(fmaxf(x, -15.f), 15.f);
    float e = __expf(2.f * x);
    return 1.f - __fdividef(2.f, e + 1.f);
}
__device__ __forceinline__ float fsig(float x) {
    x = fminf(fmaxf(x, -30.f), 30.f);
    return __fdividef(1.f, 1.f + __expf(-x));
}

// ---------------- 1) embedding gather + inline bf16 split --------------------
__global__ __launch_bounds__(128) void embed_kernel(const int* __restrict__ concepts,
                                                    const float* __restrict__ emb) {
    int row = blockIdx.x;                       // s*16 + b
    int tok = concepts[row];
    const float4* src = (const float4*)(emb + (size_t)tok * EMB);
    float4 v = src[threadIdx.x];
    ((float4*)(g_xa + (size_t)row * EMB))[threadIdx.x] = v;
    uint2 h, l;
    split4(v, h, l);
    g_a1[row * 128 + threadIdx.x] = h;
    g_a2[row * 128 + threadIdx.x] = l;
}

// ---------------- 1b) fp32 -> bf16 hi/lo split (weights only) ----------------
__global__ __launch_bounds__(256) void split_kernel(const float4* __restrict__ src,
                                                    uint2* __restrict__ d1,
                                                    uint2* __restrict__ d2, int n4) {
    int stride = gridDim.x * blockDim.x;
    for (int i = blockIdx.x * blockDim.x + threadIdx.x; i < n4; i += stride) {
        float4 v = src[i];
        uint2 h, l;
        split4(v, h, l);
        d1[i] = h;
        d2[i] = l;
    }
}

// ---------------- 2) input projection via mma.sync bf16x3 --------------------
#define MMA_BF16(c, a, b)                                                       \
    asm volatile(                                                               \
        "mma.sync.aligned.m16n8k16.row.col.f32.bf16.bf16.f32 "                  \
        "{%0,%1,%2,%3}, {%4,%5,%6,%7}, {%8,%9}, {%0,%1,%2,%3};"                 \
        : "+f"((c)[0]), "+f"((c)[1]), "+f"((c)[2]), "+f"((c)[3])                \
        : "r"((a)[0]), "r"((a)[1]), "r"((a)[2]), "r"((a)[3]),                   \
          "r"((b)[0]), "r"((b)[1]))

__global__ __launch_bounds__(256, 2) void inproj_mma_kernel(int layer,
                                                            const float* __restrict__ bias) {
    __shared__ __align__(16) unsigned short As1[128][40];
    __shared__ __align__(16) unsigned short As2[128][40];
    __shared__ __align__(16) unsigned short Ws1[128][40];
    __shared__ __align__(16) unsigned short Ws2[128][40];
    int tid = threadIdx.x, wid = tid >> 5, lane = tid & 31;
    int n0 = blockIdx.x << 7, m0 = blockIdx.y << 7;
    int wm = wid >> 2, wn = wid & 3;
    int g = lane >> 2, t4 = lane & 3;

    const uint4* A1 = (const uint4*)g_a1;
    const uint4* A2 = (const uint4*)g_a2;
    const uint4* W1 = (const uint4*)g_w1 + (size_t)layer * 131072;
    const uint4* W2 = (const uint4*)g_w2 + (size_t)layer * 131072;

    float acc[4][4][4];
#pragma unroll
    for (int mt = 0; mt < 4; mt++)
#pragma unroll
        for (int nt = 0; nt < 4; nt++)
#pragma unroll
            for (int i = 0; i < 4; i++) acc[mt][nt][i] = 0.f;

    for (int ch = 0; ch < 16; ch++) {
        int kb = (ch << 2);
        uint4 ra1[2], ra2[2], rw1[2], rw2[2];
        int r0 = (tid * 2) >> 2, c0 = (tid * 2) & 3;
        int r1 = (tid * 2 + 1) >> 2, c1 = (tid * 2 + 1) & 3;
        ra1[0] = A1[(size_t)(m0 + r0) * 64 + kb + c0];
        ra1[1] = A1[(size_t)(m0 + r1) * 64 + kb + c1];
        ra2[0] = A2[(size_t)(m0 + r0) * 64 + kb + c0];
        ra2[1] = A2[(size_t)(m0 + r1) * 64 + kb + c1];
        rw1[0] = W1[(size_t)(n0 + r0) * 64 + kb + c0];
        rw1[1] = W1[(size_t)(n0 + r1) * 64 + kb + c1];
        rw2[0] = W2[(size_t)(n0 + r0) * 64 + kb + c0];
        rw2[1] = W2[(size_t)(n0 + r1) * 64 + kb + c1];
        __syncthreads();
        *(uint4*)&As1[r0][c0 << 3] = ra1[0];
        *(uint4*)&As1[r1][c1 << 3] = ra1[1];
        *(uint4*)&As2[r0][c0 << 3] = ra2[0];
        *(uint4*)&As2[r1][c1 << 3] = ra2[1];
        *(uint4*)&Ws1[r0][c0 << 3] = rw1[0];
        *(uint4*)&Ws1[r1][c1 << 3] = rw1[1];
        *(uint4*)&Ws2[r0][c0 << 3] = rw2[0];
        *(uint4*)&Ws2[r1][c1 << 3] = rw2[1];
        __syncthreads();

#pragma unroll
        for (int k16 = 0; k16 < 2; k16++) {
            int kk = k16 << 4;
            unsigned b1f[4][2], b2f[4][2];
#pragma unroll
            for (int nt = 0; nt < 4; nt++) {
                int nr = (wn << 5) + (nt << 3) + g;
                b1f[nt][0] = *(const unsigned*)&Ws1[nr][kk + (t4 << 1)];
                b1f[nt][1] = *(const unsigned*)&Ws1[nr][kk + 8 + (t4 << 1)];
                b2f[nt][0] = *(const unsigned*)&Ws2[nr][kk + (t4 << 1)];
                b2f[nt][1] = *(const unsigned*)&Ws2[nr][kk + 8 + (t4 << 1)];
            }
#pragma unroll
            for (int mt = 0; mt < 4; mt++) {
                int mr = (wm << 6) + (mt << 4);
                unsigned a1f[4], a2f[4];
                a1f[0] = *(const unsigned*)&As1[mr + g][kk + (t4 << 1)];
                a1f[1] = *(const unsigned*)&As1[mr + g + 8][kk + (t4 << 1)];
                a1f[2] = *(const unsigned*)&As1[mr + g][kk + 8 + (t4 << 1)];
                a1f[3] = *(const unsigned*)&As1[mr + g + 8][kk + 8 + (t4 << 1)];
                a2f[0] = *(const unsigned*)&As2[mr + g][kk + (t4 << 1)];
                a2f[1] = *(const unsigned*)&As2[mr + g + 8][kk + (t4 << 1)];
                a2f[2] = *(const unsigned*)&As2[mr + g][kk + 8 + (t4 << 1)];
                a2f[3] = *(const unsigned*)&As2[mr + g + 8][kk + 8 + (t4 << 1)];
#pragma unroll
                for (int nt = 0; nt < 4; nt++) {
                    MMA_BF16(acc[mt][nt], a1f, b1f[nt]);
                    MMA_BF16(acc[mt][nt], a1f, b2f[nt]);
                    MMA_BF16(acc[mt][nt], a2f, b1f[nt]);
                }
            }
        }
    }

#pragma unroll
    for (int mt = 0; mt < 4; mt++) {
#pragma unroll
        for (int nt = 0; nt < 4; nt++) {
            int mA = m0 + (wm << 6) + (mt << 4) + g;
            int nA = n0 + (wn << 5) + (nt << 3) + (t4 << 1);
            const float* c = acc[mt][nt];
#pragma unroll
            for (int e = 0; e < 4; e++) {
                int m = mA + ((e >> 1) << 3);
                int n = nA + (e & 1);
                int s = m >> 4, b = m & 15;
                int d = n >> 10, gg = n & 1023;
                g_xproj[(size_t)((((d << 8) | s) << 10) | gg) * BATCH + b] =
                    c[e] + __ldg(&bias[n]);
            }
        }
    }
}

// ---------------- 2b) attention projections via mma.sync bf16x3 --------------
__global__ __launch_bounds__(256, 2) void attn_mma_kernel() {
    __shared__ __align__(16) unsigned short As1[128][40];
    __shared__ __align__(16) unsigned short As2[128][40];
    __shared__ __align__(16) unsigned short Ws1[128][40];
    __shared__ __align__(16) unsigned short Ws2[128][40];
    int tid = threadIdx.x, wid = tid >> 5, lane = tid & 31;
    int n0 = blockIdx.x << 7, m0 = blockIdx.y << 7;   // n0 in {0,128}
    int wm = wid >> 2, wn = wid & 3;
    int g = lane >> 2, t4 = lane & 3;
    float* __restrict__ out = (blockIdx.x == 0) ? g_p : g_cq;

    const uint4* A1 = (const uint4*)g_a1;
    const uint4* A2 = (const uint4*)g_a2;
    const uint4* W1 = (const uint4*)g_u1;
    const uint4* W2 = (const uint4*)g_u2;

    float acc[4][4][4];
#pragma unroll
    for (int mt = 0; mt < 4; mt++)
#pragma unroll
        for (int nt = 0; nt < 4; nt++)
#pragma unroll
            for (int i = 0; i < 4; i++) acc[mt][nt][i] = 0.f;

    for (int ch = 0; ch < 16; ch++) {
        int kb = (ch << 2);
        uint4 ra1[2], ra2[2], rw1[2], rw2[2];
        int r0 = (tid * 2) >> 2, c0 = (tid * 2) & 3;
        int r1 = (tid * 2 + 1) >> 2, c1 = (tid * 2 + 1) & 3;
        ra1[0] = A1[(size_t)(m0 + r0) * 64 + kb + c0];
        ra1[1] = A1[(size_t)(m0 + r1) * 64 + kb + c1];
        ra2[0] = A2[(size_t)(m0 + r0) * 64 + kb + c0];
        ra2[1] = A2[(size_t)(m0 + r1) * 64 + kb + c1];
        rw1[0] = W1[(size_t)(n0 + r0) * 64 + kb + c0];
        rw1[1] = W1[(size_t)(n0 + r1) * 64 + kb + c1];
        rw2[0] = W2[(size_t)(n0 + r0) * 64 + kb + c0];
        rw2[1] = W2[(size_t)(n0 + r1) * 64 + kb + c1];
        __syncthreads();
        *(uint4*)&As1[r0][c0 << 3] = ra1[0];
        *(uint4*)&As1[r1][c1 << 3] = ra1[1];
        *(uint4*)&As2[r0][c0 << 3] = ra2[0];
        *(uint4*)&As2[r1][c1 << 3] = ra2[1];
        *(uint4*)&Ws1[r0][c0 << 3] = rw1[0];
        *(uint4*)&Ws1[r1][c1 << 3] = rw1[1];
        *(uint4*)&Ws2[r0][c0 << 3] = rw2[0];
        *(uint4*)&Ws2[r1][c1 << 3] = rw2[1];
        __syncthreads();

#pragma unroll
        for (int k16 = 0; k16 < 2; k16++) {
            int kk = k16 << 4;
            unsigned b1f[4][2], b2f[4][2];
#pragma unroll
            for (int nt = 0; nt < 4; nt++) {
                int nr = (wn << 5) + (nt << 3) + g;
                b1f[nt][0] = *(const unsigned*)&Ws1[nr][kk + (t4 << 1)];
                b1f[nt][1] = *(const unsigned*)&Ws1[nr][kk + 8 + (t4 << 1)];
                b2f[nt][0] = *(const unsigned*)&Ws2[nr][kk + (t4 << 1)];
                b2f[nt][1] = *(const unsigned*)&Ws2[nr][kk + 8 + (t4 << 1)];
            }
#pragma unroll
            for (int mt = 0; mt < 4; mt++) {
                int mr = (wm << 6) + (mt << 4);
                unsigned a1f[4], a2f[4];
                a1f[0] = *(const unsigned*)&As1[mr + g][kk + (t4 << 1)];
                a1f[1] = *(const unsigned*)&As1[mr + g + 8][kk + (t4 << 1)];
                a1f[2] = *(const unsigned*)&As1[mr + g][kk + 8 + (t4 << 1)];
                a1f[3] = *(const unsigned*)&As1[mr + g + 8][kk + 8 + (t4 << 1)];
                a2f[0] = *(const unsigned*)&As2[mr + g][kk + (t4 << 1)];
                a2f[1] = *(const unsigned*)&As2[mr + g + 8][kk + (t4 << 1)];
                a2f[2] = *(const unsigned*)&As2[mr + g][kk + 8 + (t4 << 1)];
                a2f[3] = *(const unsigned*)&As2[mr + g + 8][kk + 8 + (t4 << 1)];
#pragma unroll
                for (int nt = 0; nt < 4; nt++) {
                    MMA_BF16(acc[mt][nt], a1f, b1f[nt]);
                    MMA_BF16(acc[mt][nt], a1f, b2f[nt]);
                    MMA_BF16(acc[mt][nt], a2f, b1f[nt]);
                }
            }
        }
    }

#pragma unroll
    for (int mt = 0; mt < 4; mt++) {
#pragma unroll
        for (int nt = 0; nt < 4; nt++) {
            int mA = m0 + (wm << 6) + (mt << 4) + g;
            int nA = (wn << 5) + (nt << 3) + (t4 << 1);   // local col 0..127
            const float* c = acc[mt][nt];
#pragma unroll
            for (int e = 0; e < 4; e++) {
                int m = mA + ((e >> 1) << 3);
                int nl = nA + (e & 1);
                int s = m >> 4, b = m & 15;
                out[(size_t)(((b << 8) + s) << 7) + nl] = c[e];
            }
        }
    }
}

// ---------------- 3) LSTM recurrence: cluster(8) + DSMEM ---------------------
// R14: publish FIRST after bar.sync; xout + bf16 split stores AFTER (off the
// cross-CTA critical path).
__global__ __launch_bounds__(256) __cluster_dims__(8, 1, 1)
void lstm_rec_kernel(int layer, const float* __restrict__ whh) {
    float* __restrict__ xout = layer ? g_xa : g_xb;
    int bx  = blockIdx.x;
    int dir = bx >> 6;
    int bgp = (bx >> 3) & 7;           // batches b0 = bgp*2, +1
    int rk  = bx & 7;                  // unit group: units j0..j0+31
    int j0  = rk << 5;
    int b0  = bgp << 1;
    int tid = threadIdx.x;
    int ks  = tid >> 5;                // k-slice 0..7 (32 k each)
    int un  = tid & 31;                // unit within group

    __shared__ __align__(16) float h_buf[2][512];     // [buf][b*256 + unit]
    __shared__ __align__(16) float part_s[8][264];    // [ks][gate g]
    __shared__ __align__(16) float hstage[64];        // [b*32 + u]
    __shared__ __align__(8)  unsigned long long mbar_store;

    unsigned sm_h    = smem_u32(&h_buf[0][0]);
    unsigned sm_mbar = smem_u32(&mbar_store);

    unsigned long long w_ull[4][16];
#pragma unroll
    for (int q = 0; q < 4; q++) {
        const float* wr = whh + (size_t)((dir << 10) + (q << 8) + j0 + un) * HID + (ks << 5);
#pragma unroll
        for (int m = 0; m < 8; m++) {
            float4 f = *(const float4*)&wr[m << 2];
            w_ull[q][m * 2]     = pack2(f.x, f.y);
            w_ull[q][m * 2 + 1] = pack2(f.z, f.w);
        }
    }
    if (tid < 128) *(float4*)&h_buf[0][tid << 2] = make_float4(0.f, 0.f, 0.f, 0.f);
    if (tid == 0) mbar_init(sm_mbar, 16u);
    __syncthreads();
    asm volatile("barrier.cluster.arrive.aligned;" ::: "memory");
    asm volatile("barrier.cluster.wait.aligned;"   ::: "memory");

    float c_reg = 0.f;
    int au = tid >> 1, ab = tid & 1;
    int xb0 = (dir << 22) + (j0 + au) * BATCH + b0 + ab;
    int xb1 = xb0 + (1 << 8) * BATCH;
    int xb2 = xb0 + (2 << 8) * BATCH;
    int xb3 = xb0 + (3 << 8) * BATCH;

    unsigned short* a1u = (unsigned short*)g_a1;
    unsigned short* a2u = (unsigned short*)g_a2;

    for (int p = 0; p < SQ; p++) {
        int t = dir ? (SQ - 1 - p) : p;
        float x0 = 0.f, x1 = 0.f, x2 = 0.f, x3 = 0.f;
        if (tid < 64) {
            x0 = __ldg(&g_xproj[xb0 + (t << 14)]);
            x1 = __ldg(&g_xproj[xb1 + (t << 14)]);
            x2 = __ldg(&g_xproj[xb2 + (t << 14)]);
            x3 = __ldg(&g_xproj[xb3 + (t << 14)]);
        }
        if (p > 0) mbar_wait(sm_mbar, (unsigned)((p - 1) & 1));

        const float* hcur = &h_buf[p & 1][0];
        unsigned long long acc[4][2];
#pragma unroll
        for (int q = 0; q < 4; q++) { acc[q][0] = 0ull; acc[q][1] = 0ull; }
#pragma unroll
        for (int b = 0; b < 2; b++) {
            const float* hb = hcur + (b << 8) + (ks << 5);
#pragma unroll
            for (int m = 0; m < 8; m++) {
                float4 h4 = *(const float4*)&hb[m << 2];
                unsigned long long h01 = pack2(h4.x, h4.y);
                unsigned long long h23 = pack2(h4.z, h4.w);
#pragma unroll
                for (int q = 0; q < 4; q++) {
                    acc[q][b] = ffma2(w_ull[q][m * 2],     h01, acc[q][b]);
                    acc[q][b] = ffma2(w_ull[q][m * 2 + 1], h23, acc[q][b]);
                }
            }
        }
#pragma unroll
        for (int q = 0; q < 4; q++) {
            float2 s0 = unpack2(acc[q][0]);
            float2 s1 = unpack2(acc[q][1]);
            *(float2*)&part_s[ks][(q << 6) + (un << 1)] =
                make_float2(s0.x + s0.y, s1.x + s1.y);
        }
        __syncthreads();

        if (tid < 64) {
            float g0 = x0, g1 = x1, g2 = x2, g3 = x3;
#pragma unroll
            for (int s2 = 0; s2 < 8; s2++) {
                g0 += part_s[s2][tid];
                g1 += part_s[s2][64 + tid];
                g2 += part_s[s2][128 + tid];
                g3 += part_s[s2][192 + tid];
            }
            c_reg = fsig(g1) * c_reg + fsig(g0) * ftanh(g2);
            float h = fsig(g3) * ftanh(c_reg);
            hstage[(ab << 5) + au] = h;
            asm volatile("bar.sync 1, 64;" ::: "memory");
            // ---- critical path: DSMEM publish + arrive FIRST --------------
            if (p + 1 < SQ && tid < 16) {
                unsigned dst = (unsigned)(tid >> 1);
                int b = tid & 1;
                unsigned off = sm_h + (((p + 1) & 1) << 11) + (b << 10) + (j0 << 2);
                unsigned ra = mapa_u32(off, dst);
                const float4* src = (const float4*)&hstage[b << 5];
#pragma unroll
                for (int i = 0; i < 8; i++) st_cluster_v4(ra + (i << 4), src[i]);
                mbar_arrive_rank(sm_mbar, dst);
            }
            // ---- off-path: xout + bf16 split stores ------------------------
            size_t xi = (size_t)((t * BATCH + b0 + ab) << 9) + (dir << 8) + j0 + au;
            xout[xi] = h;
            unsigned short hh, hl;
            split1(h, hh, hl);
            a1u[xi] = hh;
            a2u[xi] = hl;
        }
    }
    asm volatile("barrier.cluster.arrive.aligned;" ::: "memory");
    asm volatile("barrier.cluster.wait.aligned;"   ::: "memory");
}

// ---------------- 5) pairwise scores + predictions --------------------------
__global__ __launch_bounds__(256) void scores_kernel(const float* __restrict__ va,
                                                     float* __restrict__ out,
                                                     int write_pred) {
    __shared__ __align__(16) float ps[32][132];
    __shared__ __align__(16) float cs[32][132];
    __shared__ float va_s[HMD];
    int b  = blockIdx.z;
    int i0 = blockIdx.y << 5, j0 = blockIdx.x << 5;
    int tid = threadIdx.x;
    if (tid < HMD) va_s[tid] = va[tid];
#pragma unroll
    for (int i = 0; i < 4; i++) {
        int f4 = tid + (i << 8);
        int row = f4 >> 5;
        int col = (f4 & 31) << 2;
        *(float4*)&ps[row][col] =
            *(const float4*)&g_p[(size_t)(((b << 8) + i0 + row) << 7) + col];
        *(float4*)&cs[row][col] =
            *(const float4*)&g_cq[(size_t)(((b << 8) + j0 + row) << 7) + col];
    }
    __syncthreads();

    int tj = tid & 15, ti = tid >> 4;
    int ia = ti << 1, ja = tj << 1;
    float s00 = 0.f, s01 = 0.f, s10 = 0.f, s11 = 0.f;
#pragma unroll 4
    for (int h = 0; h < HMD; h++) {
        float v  = va_s[h];
        float pa = ps[ia][h],     pb = ps[ia + 1][h];
        float ca = cs[ja][h],     cb = cs[ja + 1][h];
        s00 += v * ftanh(pa + ca);
        s01 += v * ftanh(pa + cb);
        s10 += v * ftanh(pb + ca);
        s11 += v * ftanh(pb + cb);
    }
    int gi = i0 + ia, gj = j0 + ja;
    size_t base = ((size_t)b << 16) + ((size_t)gi << 8) + gj;
    out[base]           = s00;
    out[base + 1]       = s01;
    out[base + 256]     = s10;
    out[base + 257]     = s11;
    if (write_pred) {
        float* po = out + NSC;
        po[base]       = (s00 >= 0.f) ? 1.f : 0.f;
        po[base + 1]   = (s01 >= 0.f) ? 1.f : 0.f;
        po[base + 256] = (s10 >= 0.f) ? 1.f : 0.f;
        po[base + 257] = (s11 >= 0.f) ? 1.f : 0.f;
    }
}

// ---------------- launch -----------------------------------------------------
extern "C" void kernel_launch(void* const* d_in, const int* in_sizes, int n_in,
                              void* d_out, int out_size) {
    const int*   concepts = (const int*)d_in[0];
    const float* emb  = (const float*)d_in[2];
    const float* w_ih = (const float*)d_in[3];
    const float* w_hh = (const float*)d_in[4];
    const float* bias = (const float*)d_in[5];
    const float* Ua   = (const float*)d_in[6];
    const float* Wa   = (const float*)d_in[7];
    const float* va   = (const float*)d_in[8];
    float* out = (float*)d_out;

    uint2 *d_w1, *d_w2, *d_u1, *d_u2;
    cudaGetSymbolAddress((void**)&d_w1, g_w1);
    cudaGetSymbolAddress((void**)&d_w2, g_w2);
    cudaGetSymbolAddress((void**)&d_u1, g_u1);
    cudaGetSymbolAddress((void**)&d_u2, g_u2);

    embed_kernel<<<NROWS, 128>>>(concepts, emb);                       // #1 (+A split)

    // weight splits (input-constant)
    split_kernel<<<1024, 256>>>((const float4*)w_ih, d_w1, d_w2,
                                2 * 2 * G4 * EMB / 4);                 // #2
    split_kernel<<<64, 256>>>((const float4*)Ua, d_u1, d_u2,
                              HMD * INW / 4);                          // #3
    split_kernel<<<64, 256>>>((const float4*)Wa, d_u1 + HMD * INW / 4,
                              d_u2 + HMD * INW / 4, HMD * INW / 4);    // #4

    // layer 0
    inproj_mma_kernel<<<dim3(16, 32), 256>>>(0, bias);                 // #5
    lstm_rec_kernel<<<128, 256>>>(0, w_hh);                            // #6 <- ncu
    // layer 1
    inproj_mma_kernel<<<dim3(16, 32), 256>>>(1, bias + 2 * G4);
    lstm_rec_kernel<<<128, 256>>>(1, w_hh + 2 * G4 * HID);

    attn_mma_kernel<<<dim3(2, 32), 256>>>();

    int write_pred = (out_size >= 2 * NSC) ? 1 : 0;
    scores_kernel<<<dim3(8, 8, BATCH), 256>>>(va, out, write_pred);
}